// round 16
// baseline (speedup 1.0000x reference)
#include <cuda_runtime.h>
#include <cstdint>

// Problem constants (from reference setup_inputs)
#define NB 8
#define NC 64
#define HH 128
#define WW 128
#define EH 64
#define EW 64
#define THETA 10.0f

#define CSPB 16                        // channels per block
#define NCGRP (NC / CSPB)              // 4 channel groups
#define ROWS_PER_BLK 4                 // 4 warps -> 4 rows
#define NROWBLK (HH / ROWS_PER_BLK)    // 32
#define TBLK (ROWS_PER_BLK * 32)       // 128 threads
#define NSTAGE 5                       // cp.async ring depth (4 ahead)

#define CP16(dst, src) \
    asm volatile("cp.async.cg.shared.global [%0], [%1], 16;" \
                 :: "r"(dst), "l"(src) : "memory")
#define CPCOMMIT() asm volatile("cp.async.commit_group;" ::: "memory")
#define CPWAIT4()  asm volatile("cp.async.wait_group 4;"  ::: "memory")

// Packed fp32x2 ops (sm_103a): one fma-pipe instruction, two fp32 lanes.
__device__ __forceinline__ uint64_t pk(float lo, float hi) {
    uint64_t r;
    asm("mov.b64 %0, {%1, %2};" : "=l"(r) : "f"(lo), "f"(hi));
    return r;
}
__device__ __forceinline__ uint64_t fma2(uint64_t a, uint64_t b, uint64_t c) {
    uint64_t d;
    asm("fma.rn.f32x2 %0, %1, %2, %3;" : "=l"(d) : "l"(a), "l"(b), "l"(c));
    return d;
}
__device__ __forceinline__ void upk(float& lo, float& hi, uint64_t v) {
    asm("mov.b64 {%0, %1}, %2;" : "=f"(lo), "=f"(hi) : "l"(v));
}

// ---------------------------------------------------------------------------
// Fused kernel (R15 structure, deeper pipeline): per-block weight computation
// (bilinear edge upsample + softmax, boundary padding folded into weights)
// followed by a FULLY UNROLLED 16-channel apply loop fed by a warp-private
// cp.async pipeline — now 4 channels ahead in a 5-stage ring (per-warp
// commit/wait, no block barriers). Apply uses packed fma.rn.f32x2.
// ---------------------------------------------------------------------------
__global__ __launch_bounds__(TBLK, 7)
void geg_fused_kernel(const float* __restrict__ mask,
                      const float* __restrict__ edge,
                      float* __restrict__ out)
{
    // [warp][stage][row][lane] float4 = 30 KB
    __shared__ float4 sbuf[ROWS_PER_BLK][NSTAGE][3][32];

    const int t    = threadIdx.x;
    const int warp = t >> 5;
    const int lane = t & 31;

    const int rowblk = blockIdx.x;     // 0..31
    const int cgrp   = blockIdx.y;     // 0..3
    const int n      = blockIdx.z;     // 0..7

    const int y  = rowblk * ROWS_PER_BLK + warp;  // output row, 0..127
    const int x0 = lane * 4;

    const int img  = HH * WW;
    const int base = (n * NC + cgrp * CSPB) * img;

    // Clamped row offsets (OOB rows carry zero weight).
    const int off0 = max(y - 1, 0)      * WW + x0;
    const int off1 = y                  * WW + x0;
    const int off2 = min(y + 1, HH - 1) * WW + x0;

    const float* p0 = mask + base + off0;
    const float* p1 = mask + base + off1;
    const float* p2 = mask + base + off2;
    float*       po = out  + base + off1;

    const unsigned sbase =
        (unsigned)__cvta_generic_to_shared(&sbuf[warp][0][0][lane]);
    // stage stride = 1536B; row stride = 512B

    // ---- cp.async prologue: channels 0..3 in flight ----------------------
    #pragma unroll
    for (int c = 0; c < 4; c++) {
        const unsigned st = sbase + c * 1536;
        CP16(st,        p0 + c * img);
        CP16(st + 512,  p1 + c * img);
        CP16(st + 1024, p2 + c * img);
        CPCOMMIT();
    }

    // ---- weights: bilinear-upsampled edge + softmax (overlaps fill) ------
    float w[4][9];
    {
        const float* eptr = edge + n * (EH * EW);
        const float sc = 63.0f / 127.0f;   // (EH-1)/(HH-1), align_corners

        float er[3][6];
        #pragma unroll
        for (int r = 0; r < 3; r++) {
            const int gy = y - 1 + r;
            float4 ev = make_float4(0.f, 0.f, 0.f, 0.f);
            if (gy >= 0 && gy < HH) {
                const float ys = (float)gy * sc;
                const int   yi = (int)ys;
                const float wy = ys - (float)yi;
                const int   y1 = min(yi + 1, EH - 1);
                const float* r0 = eptr + yi * EW;
                const float* r1 = eptr + y1 * EW;
                float v[4];
                #pragma unroll
                for (int p = 0; p < 4; p++) {
                    const int   gx = x0 + p;
                    const float xs = (float)gx * sc;
                    const int   xi = (int)xs;
                    const float wx = xs - (float)xi;
                    const int   x1 = min(xi + 1, EW - 1);
                    const float a  = r0[xi];
                    const float b  = r0[x1];
                    const float c0 = r1[xi];
                    const float d  = r1[x1];
                    const float top = a  + (b  - a ) * wx;
                    const float bot = c0 + (d  - c0) * wx;
                    v[p] = top + (bot - top) * wy;
                }
                ev = make_float4(v[0], v[1], v[2], v[3]);
            }
            float left  = __shfl_up_sync(0xffffffffu, ev.w, 1);
            float right = __shfl_down_sync(0xffffffffu, ev.x, 1);
            if (lane == 0)  left  = 0.f;
            if (lane == 31) right = 0.f;
            er[r][0] = left; er[r][1] = ev.x; er[r][2] = ev.y;
            er[r][3] = ev.z; er[r][4] = ev.w; er[r][5] = right;
        }

        #pragma unroll
        for (int p = 0; p < 4; p++) {
            const float ec = er[1][p + 1];
            float s = 0.f;
            #pragma unroll
            for (int k = 0; k < 9; k++) {
                const float d  = ec - er[k / 3][p + (k % 3)];
                const float pw = __expf(-THETA * d * d);
                w[p][k] = pw;
                s += pw;
            }
            const float rs = 1.f / s;
            #pragma unroll
            for (int k = 0; k < 9; k++) w[p][k] *= rs;
        }

        // Fold mask zero-padding into the (normalized) weights.
        if (y == 0) {
            #pragma unroll
            for (int p = 0; p < 4; p++) { w[p][0] = 0.f; w[p][1] = 0.f; w[p][2] = 0.f; }
        }
        if (y == HH - 1) {
            #pragma unroll
            for (int p = 0; p < 4; p++) { w[p][6] = 0.f; w[p][7] = 0.f; w[p][8] = 0.f; }
        }
        if (lane == 0)  { w[0][0] = 0.f; w[0][3] = 0.f; w[0][6] = 0.f; }
        if (lane == 31) { w[3][2] = 0.f; w[3][5] = 0.f; w[3][8] = 0.f; }
    }

    // Pack weights for pixel pairs (0,1) and (2,3): 18 x 64-bit registers.
    uint64_t w01[9], w23[9];
    #pragma unroll
    for (int k = 0; k < 9; k++) {
        w01[k] = pk(w[0][k], w[1][k]);
        w23[k] = pk(w[2][k], w[3][k]);
    }

    // ---- channel loop: FULLY UNROLLED, 4-ahead ring, packed f32x2 ---------
    const float4* stp = &sbuf[warp][0][0][lane];
    const uint64_t z = 0;   // packed (0,0)

    #pragma unroll
    for (int c = 0; c < CSPB; c++) {
        if (c + 4 < CSPB) {
            const unsigned st = sbase + ((c + 4) % NSTAGE) * 1536;
            CP16(st,        p0 + (c + 4) * img);
            CP16(st + 512,  p1 + (c + 4) * img);
            CP16(st + 1024, p2 + (c + 4) * img);
        }
        CPCOMMIT();
        CPWAIT4();          // channel c's group is complete

        const int sidx = (c % NSTAGE) * 96;   // float4 units
        float4 m0 = stp[sidx];
        float4 m1 = stp[sidx + 32];
        float4 m2 = stp[sidx + 64];

        float l0 = __shfl_up_sync(0xffffffffu, m0.w, 1);
        float r0 = __shfl_down_sync(0xffffffffu, m0.x, 1);
        float l1 = __shfl_up_sync(0xffffffffu, m1.w, 1);
        float r1 = __shfl_down_sync(0xffffffffu, m1.x, 1);
        float l2 = __shfl_up_sync(0xffffffffu, m2.w, 1);
        float r2 = __shfl_down_sync(0xffffffffu, m2.x, 1);

        // Sliding 64-bit pairs per row: P0=(l,x) P1=(x,y) P2=(y,z) P3=(z,w)
        // P4=(w,r). P1/P3 are free (LDS.128 quad is reg-pair aligned).
        uint64_t acc01 = z, acc23 = z;
        {   // row 0, taps k=0..2
            uint64_t q0 = pk(l0,   m0.x), q1 = pk(m0.x, m0.y);
            uint64_t q2 = pk(m0.y, m0.z), q3 = pk(m0.z, m0.w);
            uint64_t q4 = pk(m0.w, r0);
            acc01 = fma2(w01[0], q0, acc01);  acc23 = fma2(w23[0], q2, acc23);
            acc01 = fma2(w01[1], q1, acc01);  acc23 = fma2(w23[1], q3, acc23);
            acc01 = fma2(w01[2], q2, acc01);  acc23 = fma2(w23[2], q4, acc23);
        }
        {   // row 1, taps k=3..5
            uint64_t q0 = pk(l1,   m1.x), q1 = pk(m1.x, m1.y);
            uint64_t q2 = pk(m1.y, m1.z), q3 = pk(m1.z, m1.w);
            uint64_t q4 = pk(m1.w, r1);
            acc01 = fma2(w01[3], q0, acc01);  acc23 = fma2(w23[3], q2, acc23);
            acc01 = fma2(w01[4], q1, acc01);  acc23 = fma2(w23[4], q3, acc23);
            acc01 = fma2(w01[5], q2, acc01);  acc23 = fma2(w23[5], q4, acc23);
        }
        {   // row 2, taps k=6..8
            uint64_t q0 = pk(l2,   m2.x), q1 = pk(m2.x, m2.y);
            uint64_t q2 = pk(m2.y, m2.z), q3 = pk(m2.z, m2.w);
            uint64_t q4 = pk(m2.w, r2);
            acc01 = fma2(w01[6], q0, acc01);  acc23 = fma2(w23[6], q2, acc23);
            acc01 = fma2(w01[7], q1, acc01);  acc23 = fma2(w23[7], q3, acc23);
            acc01 = fma2(w01[8], q2, acc01);  acc23 = fma2(w23[8], q4, acc23);
        }

        float a0, a1, a2, a3;
        upk(a0, a1, acc01);
        upk(a2, a3, acc23);

        *reinterpret_cast<float4*>(po + c * img) = make_float4(a0, a1, a2, a3);
    }
}

extern "C" void kernel_launch(void* const* d_in, const int* in_sizes, int n_in,
                              void* d_out, int out_size)
{
    const float* mask = (const float*)d_in[0];
    const float* edge = (const float*)d_in[1];
    if (n_in >= 2 && in_sizes[0] < in_sizes[1]) {   // defensive swap by size
        const float* tmp = mask; mask = edge; edge = tmp;
    }
    float* out = (float*)d_out;

    dim3 grid(NROWBLK, NCGRP, NB);      // 32 x 4 x 8 = 1024 blocks
    geg_fused_kernel<<<grid, TBLK>>>(mask, edge, out);
}

// round 17
// speedup vs baseline: 1.0690x; 1.0690x over previous
#include <cuda_runtime.h>
#include <cstdint>

// Problem constants (from reference setup_inputs)
#define NB 8
#define NC 64
#define HH 128
#define WW 128
#define EH 64
#define EW 64
#define THETA 10.0f

#define CSPB 16                        // channels per block
#define NCGRP (NC / CSPB)              // 4 channel groups
#define ROWS_PER_BLK 4                 // 4 warps -> 4 rows
#define NROWBLK (HH / ROWS_PER_BLK)    // 32
#define TBLK (ROWS_PER_BLK * 32)       // 128 threads
#define NSTAGE 5                       // ring depth (3 ahead + skew 1 + 1)
#define TROWS 6                        // staged halo rows per channel

#define CP16(dst, src) \
    asm volatile("cp.async.cg.shared.global [%0], [%1], 16;" \
                 :: "r"(dst), "l"(src) : "memory")
#define CPCOMMIT() asm volatile("cp.async.commit_group;" ::: "memory")
#define CPWAIT3()  asm volatile("cp.async.wait_group 3;"  ::: "memory")

// Packed fp32x2 ops (sm_103a): one fma-pipe instruction, two fp32 lanes.
__device__ __forceinline__ uint64_t pk(float lo, float hi) {
    uint64_t r;
    asm("mov.b64 %0, {%1, %2};" : "=l"(r) : "f"(lo), "f"(hi));
    return r;
}
__device__ __forceinline__ uint64_t fma2(uint64_t a, uint64_t b, uint64_t c) {
    uint64_t d;
    asm("fma.rn.f32x2 %0, %1, %2, %3;" : "=l"(d) : "l"(a), "l"(b), "l"(c));
    return d;
}
__device__ __forceinline__ void upk(float& lo, float& hi, uint64_t v) {
    asm("mov.b64 {%0, %1}, %2;" : "=f"(lo), "=f"(hi) : "l"(v));
}

// ---------------------------------------------------------------------------
// Fused kernel, block-cooperative staging: the block stages 6 halo rows per
// channel (each thread 1.5 cp.async instead of 3 — staging traffic halves,
// L2 reads drop 2.4x), 3 channels ahead in a 5-stage ring. One __syncthreads
// per channel (after wait_group) provides cross-warp visibility and bounds
// warp skew to <=1 iteration; ring depth 5 > distance 3 + skew 1, so no
// write-after-read hazard. Apply path: LDS.128 + shuffles + fma.rn.f32x2.
// ---------------------------------------------------------------------------
__global__ __launch_bounds__(TBLK, 7)
void geg_fused_kernel(const float* __restrict__ mask,
                      const float* __restrict__ edge,
                      float* __restrict__ out)
{
    // [stage][tile row][lane] float4 = 15 KB
    __shared__ float4 sbuf[NSTAGE][TROWS][32];

    const int t    = threadIdx.x;
    const int warp = t >> 5;
    const int lane = t & 31;

    const int rowblk = blockIdx.x;     // 0..31
    const int cgrp   = blockIdx.y;     // 0..3
    const int n      = blockIdx.z;     // 0..7

    const int y0 = rowblk * ROWS_PER_BLK;
    const int y  = y0 + warp;          // output row, 0..127
    const int x0 = lane * 4;

    const int img  = HH * WW;
    const int base = (n * NC + cgrp * CSPB) * img;

    // ---- cooperative staging assignment ----------------------------------
    // Stage slot s (0..191): tile row s>>5, lane col s&31. Thread t owns
    // slot t; threads t<64 also own slot 128+t (tile rows 4,5).
    const bool has2 = (t < 64);
    const int  rA   = t >> 5;                       // tile row 0..3
    const int  gyA  = min(max(y0 - 1 + rA, 0), HH - 1);
    const int  rB   = 4 + rA;                       // valid when has2
    const int  gyB  = min(max(y0 - 1 + rB, 0), HH - 1);

    const float* pA = mask + base + gyA * WW + lane * 4;
    const float* pB = mask + base + gyB * WW + lane * 4;

    const unsigned s0 =
        (unsigned)__cvta_generic_to_shared(&sbuf[0][0][0]);
    const unsigned sdA = s0 + rA * 512 + lane * 16;
    const unsigned sdB = s0 + rB * 512 + lane * 16;   // deref'd only if has2
    // stage stride = TROWS*32*16 = 3072 B

    float* po = out + base + y * WW + x0;

    // ---- prologue: channels 0..2 in flight --------------------------------
    #pragma unroll
    for (int c = 0; c < 3; c++) {
        CP16(sdA + c * 3072, pA + c * img);
        if (has2) CP16(sdB + c * 3072, pB + c * img);
        CPCOMMIT();
    }

    // ---- weights: bilinear-upsampled edge + softmax (overlaps fill) ------
    float w[4][9];
    {
        const float* eptr = edge + n * (EH * EW);
        const float sc = 63.0f / 127.0f;   // (EH-1)/(HH-1), align_corners

        float er[3][6];
        #pragma unroll
        for (int r = 0; r < 3; r++) {
            const int gy = y - 1 + r;
            float4 ev = make_float4(0.f, 0.f, 0.f, 0.f);
            if (gy >= 0 && gy < HH) {
                const float ys = (float)gy * sc;
                const int   yi = (int)ys;
                const float wy = ys - (float)yi;
                const int   y1 = min(yi + 1, EH - 1);
                const float* r0 = eptr + yi * EW;
                const float* r1 = eptr + y1 * EW;
                float v[4];
                #pragma unroll
                for (int p = 0; p < 4; p++) {
                    const int   gx = x0 + p;
                    const float xs = (float)gx * sc;
                    const int   xi = (int)xs;
                    const float wx = xs - (float)xi;
                    const int   x1 = min(xi + 1, EW - 1);
                    const float a  = r0[xi];
                    const float b  = r0[x1];
                    const float c0 = r1[xi];
                    const float d  = r1[x1];
                    const float top = a  + (b  - a ) * wx;
                    const float bot = c0 + (d  - c0) * wx;
                    v[p] = top + (bot - top) * wy;
                }
                ev = make_float4(v[0], v[1], v[2], v[3]);
            }
            float left  = __shfl_up_sync(0xffffffffu, ev.w, 1);
            float right = __shfl_down_sync(0xffffffffu, ev.x, 1);
            if (lane == 0)  left  = 0.f;
            if (lane == 31) right = 0.f;
            er[r][0] = left; er[r][1] = ev.x; er[r][2] = ev.y;
            er[r][3] = ev.z; er[r][4] = ev.w; er[r][5] = right;
        }

        #pragma unroll
        for (int p = 0; p < 4; p++) {
            const float ec = er[1][p + 1];
            float s = 0.f;
            #pragma unroll
            for (int k = 0; k < 9; k++) {
                const float d  = ec - er[k / 3][p + (k % 3)];
                const float pw = __expf(-THETA * d * d);
                w[p][k] = pw;
                s += pw;
            }
            const float rs = 1.f / s;
            #pragma unroll
            for (int k = 0; k < 9; k++) w[p][k] *= rs;
        }

        // Fold mask zero-padding into the (normalized) weights.
        if (y == 0) {
            #pragma unroll
            for (int p = 0; p < 4; p++) { w[p][0] = 0.f; w[p][1] = 0.f; w[p][2] = 0.f; }
        }
        if (y == HH - 1) {
            #pragma unroll
            for (int p = 0; p < 4; p++) { w[p][6] = 0.f; w[p][7] = 0.f; w[p][8] = 0.f; }
        }
        if (lane == 0)  { w[0][0] = 0.f; w[0][3] = 0.f; w[0][6] = 0.f; }
        if (lane == 31) { w[3][2] = 0.f; w[3][5] = 0.f; w[3][8] = 0.f; }
    }

    // Pack weights for pixel pairs (0,1) and (2,3): 18 x 64-bit registers.
    uint64_t w01[9], w23[9];
    #pragma unroll
    for (int k = 0; k < 9; k++) {
        w01[k] = pk(w[0][k], w[1][k]);
        w23[k] = pk(w[2][k], w[3][k]);
    }

    // Consumer base: warp w reads tile rows w, w+1, w+2.
    const float4* stp = &sbuf[0][warp][lane];
    const uint64_t z = 0;

    // ---- channel loop: FULLY UNROLLED, 1 barrier per channel --------------
    #pragma unroll
    for (int c = 0; c < CSPB; c++) {
        // Issue channel c+3 into ring slot (c+3)%5. Empty commit groups in
        // the tail keep wait_group accounting sound.
        if (c + 3 < CSPB) {
            const unsigned st = ((c + 3) % NSTAGE) * 3072;
            CP16(sdA + st, pA + (c + 3) * img);
            if (has2) CP16(sdB + st, pB + (c + 3) * img);
        }
        CPCOMMIT();
        CPWAIT3();          // this thread's stage-c contributions complete
        __syncthreads();    // all threads' contributions visible; skew <= 1

        const int sidx = (c % NSTAGE) * (TROWS * 32);   // float4 units
        float4 m0 = stp[sidx];
        float4 m1 = stp[sidx + 32];
        float4 m2 = stp[sidx + 64];

        float l0 = __shfl_up_sync(0xffffffffu, m0.w, 1);
        float r0 = __shfl_down_sync(0xffffffffu, m0.x, 1);
        float l1 = __shfl_up_sync(0xffffffffu, m1.w, 1);
        float r1 = __shfl_down_sync(0xffffffffu, m1.x, 1);
        float l2 = __shfl_up_sync(0xffffffffu, m2.w, 1);
        float r2 = __shfl_down_sync(0xffffffffu, m2.x, 1);

        uint64_t acc01 = z, acc23 = z;
        {   // row 0, taps k=0..2
            uint64_t q0 = pk(l0,   m0.x), q1 = pk(m0.x, m0.y);
            uint64_t q2 = pk(m0.y, m0.z), q3 = pk(m0.z, m0.w);
            uint64_t q4 = pk(m0.w, r0);
            acc01 = fma2(w01[0], q0, acc01);  acc23 = fma2(w23[0], q2, acc23);
            acc01 = fma2(w01[1], q1, acc01);  acc23 = fma2(w23[1], q3, acc23);
            acc01 = fma2(w01[2], q2, acc01);  acc23 = fma2(w23[2], q4, acc23);
        }
        {   // row 1, taps k=3..5
            uint64_t q0 = pk(l1,   m1.x), q1 = pk(m1.x, m1.y);
            uint64_t q2 = pk(m1.y, m1.z), q3 = pk(m1.z, m1.w);
            uint64_t q4 = pk(m1.w, r1);
            acc01 = fma2(w01[3], q0, acc01);  acc23 = fma2(w23[3], q2, acc23);
            acc01 = fma2(w01[4], q1, acc01);  acc23 = fma2(w23[4], q3, acc23);
            acc01 = fma2(w01[5], q2, acc01);  acc23 = fma2(w23[5], q4, acc23);
        }
        {   // row 2, taps k=6..8
            uint64_t q0 = pk(l2,   m2.x), q1 = pk(m2.x, m2.y);
            uint64_t q2 = pk(m2.y, m2.z), q3 = pk(m2.z, m2.w);
            uint64_t q4 = pk(m2.w, r2);
            acc01 = fma2(w01[6], q0, acc01);  acc23 = fma2(w23[6], q2, acc23);
            acc01 = fma2(w01[7], q1, acc01);  acc23 = fma2(w23[7], q3, acc23);
            acc01 = fma2(w01[8], q2, acc01);  acc23 = fma2(w23[8], q4, acc23);
        }

        float a0, a1, a2, a3;
        upk(a0, a1, acc01);
        upk(a2, a3, acc23);

        *reinterpret_cast<float4*>(po + c * img) = make_float4(a0, a1, a2, a3);
    }
}

extern "C" void kernel_launch(void* const* d_in, const int* in_sizes, int n_in,
                              void* d_out, int out_size)
{
    const float* mask = (const float*)d_in[0];
    const float* edge = (const float*)d_in[1];
    if (n_in >= 2 && in_sizes[0] < in_sizes[1]) {   // defensive swap by size
        const float* tmp = mask; mask = edge; edge = tmp;
    }
    float* out = (float*)d_out;

    dim3 grid(NROWBLK, NCGRP, NB);      // 32 x 4 x 8 = 1024 blocks
    geg_fused_kernel<<<grid, TBLK>>>(mask, edge, out);
}